// round 15
// baseline (speedup 1.0000x reference)
#include <cuda_runtime.h>

#define IMG      512
#define CROPPED  504
#define BATCH    16
#define TILE_W   32
#define TILE_H   72          // 7 * 72 = 504 exactly
#define HROWS    82          // TILE_H + 10 input rows
#define W2       72          // h row stride in words (8 mod 32 -> good banks)
#define NCH      8           // phase-B chunks
#define RB       9           // rows per phase-B thread (8*9 = 72)
#define NTX      16
#define NTY      7
#define TOTAL_CTAS (NTX * NTY * BATCH)   // 1792

__device__ double   g_acc;    // zero at module load; last CTA resets each call
__device__ unsigned g_count;

// h entry (r,c) at word r*W2 + 2c + 2*(c>>3)  (8B aligned, conflict-free
// for both phase-A STS.64 octets and phase-B LDS.64 octets)
__device__ __forceinline__ int hword(int r, int c) {
    return r * W2 + 2 * c + 2 * (c >> 3);
}

__global__ __launch_bounds__(256, 4) void ssim_main_kernel(
    const float* __restrict__ img1, const float* __restrict__ img2,
    float* __restrict__ out)
{
    // horizontal 11-sums per input row: {S1,S2} and {SA=S11+S22, S12}
    __shared__ float hlo_f[HROWS * W2];
    __shared__ float hhi_f[HROWS * W2];

    const int b   = blockIdx.z;
    const int tj0 = blockIdx.x * TILE_W;
    const int ti0 = blockIdx.y * TILE_H;
    const int tid = threadIdx.x;

    const size_t base = (size_t)b * 3u * IMG * IMG;   // channel 0 of batch b

    // ===== Phase A: horizontal 11-sums, vectorized gmem loads =============
    // thread (row, seg): 1-2 input rows, 8 output cols each. 24-float window
    // per image = 6 aligned LDG.128; sliding arithmetic register-resident.
    {
        const int seg = tid & 3;
        const int j0  = seg << 3;          // 0,8,16,24
        const int gjb = tj0 + j0 - 8;      // cropped-col of a[0]
        const bool xedge = (blockIdx.x == 0) || (blockIdx.x == NTX - 1);

        #pragma unroll
        for (int rr = 0; rr < 2; rr++) {
            const int row = (tid >> 2) + rr * 64;
            if (row >= HROWS) break;
            const int gi = ti0 - 5 + row;
            const bool rowok = (unsigned)gi < (unsigned)CROPPED;

            float a[24], bb[24];
            if (rowok) {
                const float4* p1 = (const float4*)(img1 + base + (size_t)(gi + 4) * IMG + (gjb + 4));
                const float4* p2 = (const float4*)(img2 + base + (size_t)(gi + 4) * IMG + (gjb + 4));
                #pragma unroll
                for (int q = 0; q < 6; q++) {
                    const float4 va = __ldg(p1 + q);
                    const float4 vb = __ldg(p2 + q);
                    a [4*q+0] = va.x; a [4*q+1] = va.y; a [4*q+2] = va.z; a [4*q+3] = va.w;
                    bb[4*q+0] = vb.x; bb[4*q+1] = vb.y; bb[4*q+2] = vb.z; bb[4*q+3] = vb.w;
                }
                if (xedge) {
                    #pragma unroll
                    for (int m = 0; m < 24; m++)
                        if ((unsigned)(gjb + m) >= (unsigned)CROPPED) { a[m] = 0.f; bb[m] = 0.f; }
                }
            } else {
                #pragma unroll
                for (int m = 0; m < 24; m++) { a[m] = 0.f; bb[m] = 0.f; }
            }

            // output col j0+t has window m = t+3 .. t+13
            float s1 = 0.f, s2 = 0.f, sA = 0.f, s12 = 0.f;
            #pragma unroll
            for (int k = 3; k < 14; k++) {
                s1  += a[k];
                s2  += bb[k];
                sA   = fmaf(a[k], a[k], fmaf(bb[k], bb[k], sA));
                s12  = fmaf(a[k], bb[k], s12);
            }
            {
                const int w = row * W2 + 18 * seg;   // hword(row, 8*seg)
                *(float2*)&hlo_f[w] = make_float2(s1, s2);
                *(float2*)&hhi_f[w] = make_float2(sA, s12);
            }
            #pragma unroll
            for (int t = 1; t < 8; t++) {
                const float an = a[t + 13], bn = bb[t + 13];
                const float ao = a[t + 2],  bo = bb[t + 2];
                s1  += an - ao;
                s2  += bn - bo;
                sA  += fmaf(an, an, bn * bn) - fmaf(ao, ao, bo * bo);
                s12 += an * bn - ao * bo;
                const int w = row * W2 + 18 * seg + 2 * t;
                *(float2*)&hlo_f[w] = make_float2(s1, s2);
                *(float2*)&hhi_f[w] = make_float2(sA, s12);
            }
        }
    }
    __syncthreads();

    // ===== Phase B: vertical 11-sliding + SSIM ============================
    // j = tid&31 (col), chunk = tid>>5 (0..7), 9 rows/thread (8*9 = 72 = TILE_H,
    // exact fit -> no pad rows, no double counting). Max h read = r0+7+11 = 81.
    const float C1  = 6.5025f;                 // (0.01*255)^2
    const float C2  = 58.5225f;                // (0.03*255)^2
    const float inv = 1.0f / 121.0f;
    const float SCL = 1.52587890625e-5f;       // 2^-16 pre-scale

    float local = 0.0f;
    {
        const int j  = tid & 31;
        const int r0 = (tid >> 5) * RB;
        const int cw = 2 * j + 2 * (j >> 3);   // column word offset
        const bool colok = (tj0 + j) < CROPPED;

        float S1 = 0.f, S2 = 0.f, SA = 0.f, S12 = 0.f;
        #pragma unroll
        for (int k = 0; k < 11; k++) {
            const float2 lo = *(const float2*)&hlo_f[(r0 + k) * W2 + cw];
            const float2 hi = *(const float2*)&hhi_f[(r0 + k) * W2 + cw];
            S1 += lo.x; S2 += lo.y; SA += hi.x; S12 += hi.y;
        }

        float n[RB], d[RB];
        #pragma unroll
        for (int t = 0; t < RB; t++) {
            const int r = r0 + t;
            if (colok) {   // ti0 + r < 504 always (7*72 = 504 exact)
                const float mu1  = S1 * inv;
                const float mu2  = S2 * inv;
                const float m1s  = mu1 * mu1;
                const float m2s  = mu2 * mu2;
                const float m12  = mu1 * mu2;
                const float sgA  = SA  * inv - m1s - m2s;   // sig1^2 + sig2^2
                const float sg12 = S12 * inv - m12;
                const float num  = (2.0f * m12 + C1) * (2.0f * sg12 + C2);
                const float den  = (m1s + m2s + C1) * (sgA + C2);
                n[t] = num * SCL;
                d[t] = den * SCL;
            } else {
                n[t] = 0.0f;
                d[t] = 1.0f;
            }
            if (t < RB - 1) {   // slide: add h row r+11, drop h row r
                const float2 loa = *(const float2*)&hlo_f[(r + 11) * W2 + cw];
                const float2 los = *(const float2*)&hlo_f[r * W2 + cw];
                const float2 hia = *(const float2*)&hhi_f[(r + 11) * W2 + cw];
                const float2 his = *(const float2*)&hhi_f[r * W2 + cw];
                S1  += loa.x - los.x;
                S2  += loa.y - los.y;
                SA  += hia.x - his.x;
                S12 += hia.y - his.y;
            }
        }

        // 9 ratios with 2 MUFU rcp: groups of 4 and 5
        const float n01 = n[0] * d[1] + n[1] * d[0];
        const float d01 = d[0] * d[1];
        const float n23 = n[2] * d[3] + n[3] * d[2];
        const float d23 = d[2] * d[3];
        const float N4  = n01 * d23 + n23 * d01;
        const float D4  = d01 * d23;

        const float n45 = n[4] * d[5] + n[5] * d[4];
        const float d45 = d[4] * d[5];
        const float n67 = n[6] * d[7] + n[7] * d[6];
        const float d67 = d[6] * d[7];
        const float n47 = n45 * d67 + n67 * d45;
        const float d47 = d45 * d67;
        const float N5  = n47 * d[8] + n[8] * d47;
        const float D5  = d47 * d[8];

        local = __fdividef(N4, D4) + __fdividef(N5, D5);
    }

    // ===== Block reduction -> one double atomic ===========================
    #pragma unroll
    for (int o = 16; o > 0; o >>= 1)
        local += __shfl_down_sync(0xffffffffu, local, o);

    __shared__ float warpsum[8];
    if ((tid & 31) == 0) warpsum[tid >> 5] = local;
    __syncthreads();

    if (tid == 0) {
        float v = warpsum[0];
        #pragma unroll
        for (int w = 1; w < 8; w++) v += warpsum[w];
        atomicAdd(&g_acc, (double)v);

        // ---- last-CTA finalize ----
        __threadfence();
        const unsigned ticket = atomicAdd(&g_count, 1u);
        if (ticket == TOTAL_CTAS - 1) {
            const double acc = g_acc;
            out[0] = (float)(acc / ((double)BATCH * CROPPED * CROPPED));
            g_acc   = 0.0;   // reset for next graph replay
            g_count = 0u;
            __threadfence();
        }
    }
}

extern "C" void kernel_launch(void* const* d_in, const int* in_sizes, int n_in,
                              void* d_out, int out_size)
{
    const float* img1 = (const float*)d_in[0];
    const float* img2 = (const float*)d_in[1];
    float* out = (float*)d_out;

    dim3 grid(NTX, NTY, BATCH);
    ssim_main_kernel<<<grid, 256>>>(img1, img2, out);
}